// round 5
// baseline (speedup 1.0000x reference)
#include <cuda_runtime.h>
#include <cstddef>

#define G_CELLS 8000
#define T_STEPS 730
#define PF 5              // 730 = 5 * 146, exact
#define NC 2              // independent cells per thread (ILP)
#define NTHREADS 32
#define NBLOCKS 125       // 125*32*2 = 8000
#define HALF (G_CELLS / NC)
#define NEARZERO_F 1e-5f

__device__ __forceinline__ float ex2f_(float x) {
    float r; asm("ex2.approx.f32 %0, %1;" : "=f"(r) : "f"(x)); return r;
}
__device__ __forceinline__ float lg2f_(float x) {
    float r; asm("lg2.approx.f32 %0, %1;" : "=f"(r) : "f"(x)); return r;
}

__global__ __launch_bounds__(NTHREADS, 1) void hbv_kernel(
    const float* __restrict__ xphy,    // [730, 8000, 3] (P, T, PET)
    const float* __restrict__ params,  // [730, 8000, 14]
    float* __restrict__ out)           // [730, 8000]
{
    const int tid = blockIdx.x * NTHREADS + threadIdx.x;   // 0..3999
    if (tid >= HALF) return;

    // BETA, FC, K0, K1, K2, LP, PERCmax, UZL, TT, CFMAX, CFR, CWH, BETAET, C
    const float lo[14] = {1.0f, 50.0f, 0.05f, 0.01f, 0.001f, 0.2f, 0.0f,
                          0.0f, -2.5f, 0.5f, 0.0f, 0.0f, 0.3f, 0.0f};
    const float hi[14] = {6.0f, 1000.0f, 0.9f, 0.5f, 0.2f, 1.0f, 10.0f,
                          100.0f, 2.5f, 10.0f, 0.1f, 0.2f, 5.0f, 1.0f};

    // ---- per-cell constants ----
    float BETA[NC], FC[NC], PERCmax[NC], TT[NC], CFMAX[NC], CFRCF[NC],
          CWH[NC], C[NC], invFC[NC], clgA[NC], clgB[NC], sFCc[NC],
          oneK0[NC], K0UZL[NC], oneK1[NC], K2v[NC], BETAET[NC];

#pragma unroll
    for (int c = 0; c < NC; ++c) {
        const int g = tid + c * HALF;
        const float* pr =
            params + ((size_t)(T_STEPS - 1) * G_CELLS + (size_t)g) * 14;
        float phy[14];
#pragma unroll
        for (int i = 0; i < 14; i++) {
            const float s = 1.0f / (1.0f + __expf(-pr[i]));
            phy[i] = fmaf(s, hi[i] - lo[i], lo[i]);
        }
        BETA[c] = phy[0];  FC[c] = phy[1];
        const float K0 = phy[2], K1 = phy[3];
        K2v[c] = phy[4];
        const float LP = phy[5];
        PERCmax[c] = phy[6];
        const float UZL = phy[7];
        TT[c] = phy[8];  CFMAX[c] = phy[9];
        CFRCF[c] = phy[10] * phy[9];
        CWH[c] = phy[11]; BETAET[c] = phy[12]; C[c] = phy[13];

        invFC[c] = 1.0f / FC[c];
        clgA[c]  = BETA[c]   * lg2f_(invFC[c]);
        clgB[c]  = BETAET[c] * lg2f_(1.0f / (LP * FC[c]));
        sFCc[c]  = BETAET[c] * lg2f_(1.0f / LP);
        oneK0[c] = 1.0f - K0;
        K0UZL[c] = K0 * UZL;
        oneK1[c] = 1.0f - K1;
    }

    // ---- per-cell state ----
    float SP[NC], MW[NC], SM[NC], SUZ[NC], SLZ[NC], CSLZ[NC], omcf[NC];
#pragma unroll
    for (int c = 0; c < NC; ++c) {
        SP[c] = MW[c] = SM[c] = SUZ[c] = SLZ[c] = 0.001f;
        CSLZ[c] = C[c] * 0.001f;
        omcf[c] = 1.0f - CSLZ[c] * invFC[c];
    }

    // ---- prefetch ring buffers (input-derived, state-independent) ----
    float rRAIN[NC][PF], rSNOW[NC][PF], rW[NC][PF], rPET[NC][PF];
    const float* xp[NC];
#pragma unroll
    for (int c = 0; c < NC; ++c)
        xp[c] = xphy + (size_t)(tid + c * HALF) * 3;

#pragma unroll
    for (int i = 0; i < PF; i++) {
#pragma unroll
        for (int c = 0; c < NC; ++c) {
            const float P = xp[c][0], Tm = xp[c][1], PE = xp[c][2];
            xp[c] += G_CELLS * 3;
            const bool rain = (Tm >= TT[c]);
            rRAIN[c][i] = rain ? P : 0.0f;
            rSNOW[c][i] = rain ? 0.0f : P;
            rW[c][i]    = (rain ? CFMAX[c] : CFRCF[c]) * (Tm - TT[c]);
            rPET[c][i]  = PE;
        }
    }

    float* op[NC];
#pragma unroll
    for (int c = 0; c < NC; ++c) op[c] = out + tid + c * HALF;

    auto step = [&](int c, float RAIN, float SNOW, float w, float PETt) {
        // --- snow (state-only updates) ---
        const float SP1 = SP[c] + SNOW;
        const float transfer = fminf(fmaxf(w, -MW[c]), SP1);
        const float SPd = SP1 - transfer;
        const float MW2 = MW[c] + transfer;
        const float v   = fmaf(-CWH[c], SPd, MW2);
        const float tosoil = fmaxf(v, 0.0f);
        SP[c] = SPd;
        MW[c] = MW2 - tosoil;
        const float inflow = RAIN + tosoil;
        const float u  = SM[c] + RAIN;
        const float t1 = fmaxf(u + v, u);              // SM + inflow

        // --- SM critical cycle ---
        const float s1 = fminf(fmaf(BETA[c], lg2f_(SM[c]), clgA[c]), 0.0f);
        const float e1 = ex2f_(s1);                    // min((SM/FC)^B, 1)
        const float SM1 = fmaf(-inflow, e1, t1);       // >= SM guaranteed
        const float SM2 = fminf(SM1, FC[c]);
        const float s2 = fminf(fmaf(BETAET[c], lg2f_(SM1), clgB[c]), sFCc[c]);
        const float e2 = ex2f_(s2);
        const float floor3 = fmaxf(SM2 - PETt, NEARZERO_F);
        const float SM3 = fmaxf(fmaf(-PETt, e2, SM2), floor3);
        const float a = fmaf(omcf[c], SM3, CSLZ[c]);
        const float SMn = fmaxf(fminf(a, SM3 + SLZ[c]), SM3);
        const float cap = SMn - SM3;
        SM[c] = SMn;

        // --- response (off-path) ---
        const float SUZ1 = SUZ[c] + (t1 - SM2);
        const float PERC = fminf(SUZ1, PERCmax[c]);
        const float SUZ2 = fmaxf(SUZ1 - PERCmax[c], 0.0f);
        const float SUZ3 = fminf(SUZ2, fmaf(oneK0[c], SUZ2, K0UZL[c]));
        SUZ[c] = oneK1[c] * SUZ3;
        const float Q01 = SUZ2 - SUZ[c];

        const float SLZ1 = fmaxf(SLZ[c] - cap, NEARZERO_F) + PERC;
        const float Q2 = K2v[c] * SLZ1;
        SLZ[c] = SLZ1 - Q2;
        CSLZ[c] = C[c] * SLZ[c];
        omcf[c] = fmaf(-CSLZ[c], invFC[c], 1.0f);

        *op[c] = Q01 + Q2;
        op[c] += G_CELLS;
    };

    // Main: 145 PF-blocks (725 steps), branchless always-valid prefetch.
    for (int blk = 0; blk < (T_STEPS / PF) - 1; ++blk) {
#pragma unroll
        for (int i = 0; i < PF; ++i) {
#pragma unroll
            for (int c = 0; c < NC; ++c) {
                const float RAIN = rRAIN[c][i], SNOW = rSNOW[c][i];
                const float w = rW[c][i], PE = rPET[c][i];
                // prefetch + input-only precompute for step t+PF
                const float P = xp[c][0], Tm = xp[c][1], PEn = xp[c][2];
                xp[c] += G_CELLS * 3;
                const bool rain = (Tm >= TT[c]);
                rRAIN[c][i] = rain ? P : 0.0f;
                rSNOW[c][i] = rain ? 0.0f : P;
                rW[c][i]    = (rain ? CFMAX[c] : CFRCF[c]) * (Tm - TT[c]);
                rPET[c][i]  = PEn;
                step(c, RAIN, SNOW, w, PE);
            }
        }
    }
    // Epilogue: last PF steps, no prefetch.
#pragma unroll
    for (int i = 0; i < PF; ++i) {
#pragma unroll
        for (int c = 0; c < NC; ++c) {
            step(c, rRAIN[c][i], rSNOW[c][i], rW[c][i], rPET[c][i]);
        }
    }
}

extern "C" void kernel_launch(void* const* d_in, const int* in_sizes, int n_in,
                              void* d_out, int out_size) {
    const float* xphy   = (const float*)d_in[0];   // 730*8000*3
    const float* params = (const float*)d_in[1];   // 730*8000*14
    float* out = (float*)d_out;                    // 730*8000

    hbv_kernel<<<NBLOCKS, NTHREADS>>>(xphy, params, out);
}

// round 6
// speedup vs baseline: 1.3955x; 1.3955x over previous
#include <cuda_runtime.h>
#include <cstddef>

#define G_CELLS 8000
#define T_STEPS 730
#define PF 5              // pipeline depth; 720 = 5*144 main iterations
#define NEARZERO_F 1e-5f

__device__ __forceinline__ float ex2f_(float x) {
    float r; asm("ex2.approx.f32 %0, %1;" : "=f"(r) : "f"(x)); return r;
}
__device__ __forceinline__ float lg2f_(float x) {
    float r; asm("lg2.approx.f32 %0, %1;" : "=f"(r) : "f"(x)); return r;
}

__global__ __launch_bounds__(64, 1) void hbv_kernel(
    const float* __restrict__ xphy,    // [730, 8000, 3] (P, T, PET)
    const float* __restrict__ params,  // [730, 8000, 14]
    float* __restrict__ out)           // [730, 8000]
{
    const int g = blockIdx.x * blockDim.x + threadIdx.x;
    if (g >= G_CELLS) return;

    // BETA, FC, K0, K1, K2, LP, PERCmax, UZL, TT, CFMAX, CFR, CWH, BETAET, C
    const float lo[14] = {1.0f, 50.0f, 0.05f, 0.01f, 0.001f, 0.2f, 0.0f,
                          0.0f, -2.5f, 0.5f, 0.0f, 0.0f, 0.3f, 0.0f};
    const float hi[14] = {6.0f, 1000.0f, 0.9f, 0.5f, 0.2f, 1.0f, 10.0f,
                          100.0f, 2.5f, 10.0f, 0.1f, 0.2f, 5.0f, 1.0f};

    const float* pr = params + ((size_t)(T_STEPS - 1) * G_CELLS + (size_t)g) * 14;
    float phy[14];
#pragma unroll
    for (int i = 0; i < 14; i++) {
        const float s = 1.0f / (1.0f + __expf(-pr[i]));
        phy[i] = fmaf(s, hi[i] - lo[i], lo[i]);
    }
    const float BETA = phy[0],  FC = phy[1],     K0 = phy[2],  K1 = phy[3];
    const float K2 = phy[4],    LP = phy[5],     PERCmax = phy[6];
    const float UZL = phy[7],   TT = phy[8],     CFMAX = phy[9];
    const float CFR = phy[10],  CWH = phy[11],   BETAET = phy[12], C = phy[13];

    const float invFC   = 1.0f / FC;
    const float CFRCF   = CFR * CFMAX;
    const float clgA  = BETA   * lg2f_(invFC);
    const float clgB  = BETAET * lg2f_(1.0f / (LP * FC));
    const float sFCc  = BETAET * lg2f_(1.0f / LP);
    const float oneK0 = 1.0f - K0;
    const float K0UZL = K0 * UZL;
    const float oneK1 = 1.0f - K1;

    // hydrologic (chain) state
    float SM = 0.001f, SUZ = 0.001f, SLZ = 0.001f;
    float CSLZ = C * SLZ;
    float omcf = 1.0f - CSLZ * invFC;
    // snow lookahead state (independent recurrence, runs PF steps ahead)
    float SPa = 0.001f, MWa = 0.001f;

    // Snow advance: consumes raw inputs for one step, returns inflow.
    auto snow_adv = [&](float P, float Tm) -> float {
        const bool  rain = (Tm >= TT);
        const float RAIN = rain ? P : 0.0f;
        const float SNOW = rain ? 0.0f : P;
        const float w    = (rain ? CFMAX : CFRCF) * (Tm - TT);
        const float SP1  = SPa + SNOW;
        const float transfer = fminf(fmaxf(w, -MWa), SP1);
        SPa = SP1 - transfer;
        const float MW2 = MWa + transfer;
        const float v   = fmaf(-CWH, SPa, MW2);
        const float tosoil = fmaxf(v, 0.0f);
        MWa = MW2 - tosoil;
        return RAIN + tosoil;
    };

    // Processed ring (inflow, PET) for steps t..t+PF-1, and raw-input ring
    // for steps t+PF..t+2PF-1. Loads look ahead 2*PF = 10 steps (~2000 cyc).
    float rInf[PF], rPET[PF];
    float rawP[PF], rawT[PF], rawE[PF];

    const float* xb = xphy + (size_t)g * 3;
#pragma unroll
    for (int i = 0; i < PF; i++) {           // steps 0..4: load + snow now
        const float* p = xb + (size_t)i * G_CELLS * 3;
        rInf[i] = snow_adv(p[0], p[1]);
        rPET[i] = p[2];
    }
#pragma unroll
    for (int i = 0; i < PF; i++) {           // steps 5..9: raw ring
        const float* p = xb + (size_t)(PF + i) * G_CELLS * 3;
        rawP[i] = p[0]; rawT[i] = p[1]; rawE[i] = p[2];
    }

    const float* xnext = xb + (size_t)(2 * PF) * G_CELLS * 3;  // step 10
    float* op = out + g;

    // Live step: SM chain + response only (snow precomputed).
    auto step = [&](float inflow, float PETt) {
        const float t1 = SM + inflow;
        const float s1 = fminf(fmaf(BETA, lg2f_(SM), clgA), 0.0f);
        const float e1 = ex2f_(s1);                 // min((SM/FC)^B, 1)
        const float SM1 = fmaf(-inflow, e1, t1);    // >= SM guaranteed
        const float SM2 = fminf(SM1, FC);
        const float s2 = fminf(fmaf(BETAET, lg2f_(SM1), clgB), sFCc);
        const float e2 = ex2f_(s2);
        const float floor3 = fmaxf(SM2 - PETt, NEARZERO_F);
        const float SM3 = fmaxf(fmaf(-PETt, e2, SM2), floor3);
        const float a = fmaf(omcf, SM3, CSLZ);
        const float SMn = fmaxf(fminf(a, SM3 + SLZ), SM3);
        const float cap = SMn - SM3;
        SM = SMn;

        const float SUZ1 = SUZ + (t1 - SM2);        // + recharge + excess
        const float PERC = fminf(SUZ1, PERCmax);
        const float SUZ2 = fmaxf(SUZ1 - PERCmax, 0.0f);
        const float SUZ3 = fminf(SUZ2, fmaf(oneK0, SUZ2, K0UZL));
        SUZ = oneK1 * SUZ3;
        const float Q01 = SUZ2 - SUZ;

        const float SLZ1 = fmaxf(SLZ - cap, NEARZERO_F) + PERC;
        const float Q2 = K2 * SLZ1;
        SLZ = SLZ1 - Q2;
        CSLZ = C * SLZ;
        omcf = fmaf(-CSLZ, invFC, 1.0f);

        *op = Q01 + Q2;
        op += G_CELLS;
    };

    // Main: t = 0..719 (144 blocks of PF).
    for (int blk = 0; blk < (T_STEPS - 2 * PF) / PF; ++blk) {
#pragma unroll
        for (int i = 0; i < PF; ++i) {
            const float inflow = rInf[i], PE = rPET[i];
            // snow advance for step t+PF from raw ring (data loaded 5 iters ago)
            const float P = rawP[i], Tm = rawT[i], PEn = rawE[i];
            rInf[i] = snow_adv(P, Tm);
            rPET[i] = PEn;
            // load step t+2PF into raw ring (consumed 5 iters from now)
            rawP[i] = xnext[0]; rawT[i] = xnext[1]; rawE[i] = xnext[2];
            xnext += (size_t)G_CELLS * 3;
            step(inflow, PE);
        }
    }
    // Epilogue A: t = 720..724 — snow advance from raw ring, no load.
#pragma unroll
    for (int i = 0; i < PF; ++i) {
        const float inflow = rInf[i], PE = rPET[i];
        rInf[i] = snow_adv(rawP[i], rawT[i]);
        rPET[i] = rawE[i];
        step(inflow, PE);
    }
    // Epilogue B: t = 725..729 — consume only.
#pragma unroll
    for (int i = 0; i < PF; ++i) {
        step(rInf[i], rPET[i]);
    }
}

extern "C" void kernel_launch(void* const* d_in, const int* in_sizes, int n_in,
                              void* d_out, int out_size) {
    const float* xphy   = (const float*)d_in[0];   // 730*8000*3
    const float* params = (const float*)d_in[1];   // 730*8000*14
    float* out = (float*)d_out;                    // 730*8000

    const int threads = 64;
    const int blocks  = (G_CELLS + threads - 1) / threads;  // 125
    hbv_kernel<<<blocks, threads>>>(xphy, params, out);
}

// round 7
// speedup vs baseline: 1.7205x; 1.2329x over previous
#include <cuda_runtime.h>
#include <cstddef>

#define G_CELLS 8000
#define T_STEPS 730
#define CH 10              // steps per chunk; 730 = 10 * 73
#define NCHUNK 73
#define CPB 64             // cells per block; 8000 = 125 * 64
#define NEARZERO_F 1e-5f

__device__ __forceinline__ float ex2f_(float x) {
    float r; asm("ex2.approx.f32 %0, %1;" : "=f"(r) : "f"(x)); return r;
}
__device__ __forceinline__ float lg2f_(float x) {
    float r; asm("lg2.approx.f32 %0, %1;" : "=f"(r) : "f"(x)); return r;
}

// Named barriers: full0=1, full1=2 (producer->consumer),
//                 free0=3, free1=4 (consumer->producer). count = 128 threads.
#define BAR_SYNC(id)   asm volatile("bar.sync %0, 128;"   :: "r"(id) : "memory")
#define BAR_ARRIVE(id) asm volatile("bar.arrive %0, 128;" :: "r"(id) : "memory")

__global__ __launch_bounds__(128, 1) void hbv_kernel(
    const float* __restrict__ xphy,    // [730, 8000, 3] (P, T, PET)
    const float* __restrict__ params,  // [730, 8000, 14]
    float* __restrict__ out)           // [730, 8000]
{
    __shared__ float2 buf[2][CH][CPB];   // (inflow, PET) double-buffered ring

    const int tid  = threadIdx.x;
    const int lane = tid & 63;                 // cell slot within block
    const bool is_producer = (tid >= 64);
    const int g = blockIdx.x * CPB + lane;     // always < 8000

    // BETA, FC, K0, K1, K2, LP, PERCmax, UZL, TT, CFMAX, CFR, CWH, BETAET, C
    const float lo[14] = {1.0f, 50.0f, 0.05f, 0.01f, 0.001f, 0.2f, 0.0f,
                          0.0f, -2.5f, 0.5f, 0.0f, 0.0f, 0.3f, 0.0f};
    const float hi[14] = {6.0f, 1000.0f, 0.9f, 0.5f, 0.2f, 1.0f, 10.0f,
                          100.0f, 2.5f, 10.0f, 0.1f, 0.2f, 5.0f, 1.0f};

    const float* pr = params + ((size_t)(T_STEPS - 1) * G_CELLS + (size_t)g) * 14;
    float phy[14];
#pragma unroll
    for (int i = 0; i < 14; i++) {
        const float s = 1.0f / (1.0f + __expf(-pr[i]));
        phy[i] = fmaf(s, hi[i] - lo[i], lo[i]);
    }

    if (is_producer) {
        // ---------------- PRODUCER: snow recurrence + input loads ----------------
        const float TT = phy[8], CFMAX = phy[9], CWH = phy[11];
        const float CFRCF = phy[10] * phy[9];

        float SP = 0.001f, MW = 0.001f;

        auto snow_adv = [&](float P, float Tm) -> float {
            const bool  rain = (Tm >= TT);
            const float RAIN = rain ? P : 0.0f;
            const float SNOW = rain ? 0.0f : P;
            const float w    = (rain ? CFMAX : CFRCF) * (Tm - TT);
            const float SP1  = SP + SNOW;
            const float transfer = fminf(fmaxf(w, -MW), SP1);
            SP = SP1 - transfer;
            const float MW2 = MW + transfer;
            const float v   = fmaf(-CWH, SP, MW2);
            const float tosoil = fmaxf(v, 0.0f);
            MW = MW2 - tosoil;
            return RAIN + tosoil;
        };

        // Raw-input ring: holds next chunk's inputs (loaded one chunk early).
        float rP[CH], rT[CH], rE[CH];
        const float* xp = xphy + (size_t)g * 3;     // step 0
#pragma unroll
        for (int i = 0; i < CH; i++) {
            rP[i] = xp[0]; rT[i] = xp[1]; rE[i] = xp[2];
            xp += (size_t)G_CELLS * 3;
        }
        // Main chunks 0..NCHUNK-2: compute chunk k, load chunk k+1.
        for (int k = 0; k < NCHUNK - 1; ++k) {
            if (k >= 2) BAR_SYNC(3 + (k & 1));      // wait: slot free
            const int s = k & 1;
#pragma unroll
            for (int i = 0; i < CH; i++) {
                const float P = rP[i], Tm = rT[i], PE = rE[i];
                rP[i] = xp[0]; rT[i] = xp[1]; rE[i] = xp[2];
                xp += (size_t)G_CELLS * 3;
                const float inflow = snow_adv(P, Tm);
                buf[s][i][lane] = make_float2(inflow, PE);
            }
            asm volatile("membar.cta;" ::: "memory");  // order STS before arrive
            BAR_ARRIVE(1 + (k & 1));                   // signal: slot full
        }
        // Final chunk NCHUNK-1: no loads.
        {
            const int k = NCHUNK - 1;
            BAR_SYNC(3 + (k & 1));
            const int s = k & 1;
#pragma unroll
            for (int i = 0; i < CH; i++) {
                const float inflow = snow_adv(rP[i], rT[i]);
                buf[s][i][lane] = make_float2(inflow, rE[i]);
            }
            asm volatile("membar.cta;" ::: "memory");
            BAR_ARRIVE(1 + (k & 1));
        }
    } else {
        // ---------------- CONSUMER: SM/SUZ/SLZ chain + output ----------------
        const float BETA = phy[0], FC = phy[1], K0 = phy[2], K1 = phy[3];
        const float K2 = phy[4], LP = phy[5], PERCmax = phy[6], UZL = phy[7];
        const float BETAET = phy[12], C = phy[13];

        const float invFC = 1.0f / FC;
        const float clgA  = BETA   * lg2f_(invFC);
        const float clgB  = BETAET * lg2f_(1.0f / (LP * FC));
        const float sFCc  = BETAET * lg2f_(1.0f / LP);
        const float oneK0 = 1.0f - K0;
        const float K0UZL = K0 * UZL;
        const float oneK1 = 1.0f - K1;

        float SM = 0.001f, SUZ = 0.001f, SLZ = 0.001f;
        float CSLZ = C * SLZ;
        float omcf = 1.0f - CSLZ * invFC;

        float* op = out + g;

        for (int k = 0; k < NCHUNK; ++k) {
            BAR_SYNC(1 + (k & 1));                  // wait: slot full
            const int s = k & 1;
            float2 v[CH];
#pragma unroll
            for (int i = 0; i < CH; i++) v[i] = buf[s][i][lane];

#pragma unroll
            for (int i = 0; i < CH; i++) {
                const float inflow = v[i].x, PETt = v[i].y;

                const float t1 = SM + inflow;
                const float s1 = fminf(fmaf(BETA, lg2f_(SM), clgA), 0.0f);
                const float e1 = ex2f_(s1);              // min((SM/FC)^B, 1)
                const float SM1 = fmaf(-inflow, e1, t1); // >= SM guaranteed
                const float SM2 = fminf(SM1, FC);
                const float s2 = fminf(fmaf(BETAET, lg2f_(SM1), clgB), sFCc);
                const float e2 = ex2f_(s2);
                const float floor3 = fmaxf(SM2 - PETt, NEARZERO_F);
                const float SM3 = fmaxf(fmaf(-PETt, e2, SM2), floor3);
                const float a = fmaf(omcf, SM3, CSLZ);
                const float SMn = fmaxf(fminf(a, SM3 + SLZ), SM3);
                const float cap = SMn - SM3;
                SM = SMn;

                const float SUZ1 = SUZ + (t1 - SM2);     // + recharge + excess
                const float PERC = fminf(SUZ1, PERCmax);
                const float SUZ2 = fmaxf(SUZ1 - PERCmax, 0.0f);
                const float SUZ3 = fminf(SUZ2, fmaf(oneK0, SUZ2, K0UZL));
                SUZ = oneK1 * SUZ3;
                const float Q01 = SUZ2 - SUZ;

                const float SLZ1 = fmaxf(SLZ - cap, NEARZERO_F) + PERC;
                const float Q2 = K2 * SLZ1;
                SLZ = SLZ1 - Q2;
                CSLZ = C * SLZ;
                omcf = fmaf(-CSLZ, invFC, 1.0f);

                *op = Q01 + Q2;
                op += G_CELLS;
            }
            BAR_ARRIVE(3 + (k & 1));                // signal: slot free
        }
    }
}

extern "C" void kernel_launch(void* const* d_in, const int* in_sizes, int n_in,
                              void* d_out, int out_size) {
    const float* xphy   = (const float*)d_in[0];   // 730*8000*3
    const float* params = (const float*)d_in[1];   // 730*8000*14
    float* out = (float*)d_out;                    // 730*8000

    hbv_kernel<<<125, 128>>>(xphy, params, out);   // 125 * 64 cells = 8000
}